// round 10
// baseline (speedup 1.0000x reference)
#include <cuda_runtime.h>
#include <math.h>

// Problem constants (fixed by dataset)
#define N_NODES 50000
#define N_EDGES 800000
#define XCOLS   161       // NFEAT(128) + EXTRA(32) + 1
#define KTOP    71        // NN + 1
#define EPS_BN  1e-5

// ---------------- device scratch (static, allocation-free) ----------------
__device__ float   g_h  [N_NODES * 128];
__device__ float   g_s  [N_NODES * 128];
__device__ float   g_agg[N_NODES * 128];
__device__ double  g_colsum[128];
__device__ double  g_colsq [128];
__device__ float   g_mean[128];
__device__ float   g_rstd[128];
__device__ float   g_m[N_NODES];
__device__ unsigned g_minkey;
__device__ float   g_thresh;

// monotonic float<->uint key (ascending uint == ascending float)
__device__ __forceinline__ unsigned fkey(float x) {
    unsigned u = __float_as_uint(x);
    return (u & 0x80000000u) ? ~u : (u | 0x80000000u);
}
__device__ __forceinline__ float kinv(unsigned k) {
    unsigned u = (k & 0x80000000u) ? (k & 0x7FFFFFFFu) : ~k;
    return __uint_as_float(u);
}

// ---------------- GEMM: C[n,NOUT] = A[n,K] @ W[K,NOUT] (+bias,relu) -------
// block = 256 threads. tx = tid&31 -> column lane, ty = tid>>5 -> row group.
// Block tile: 128 rows x NOUT cols. Each thread: 16 rows x NOUT/32 cols.
// A tile + full W staged in dynamic shared memory. Coalesced stores.
template <int K, int NOUT, bool BIAS_RELU>
__global__ void __launch_bounds__(256)
gemm_kernel(const float* __restrict__ A, int lda,
            const float* __restrict__ W, const float* __restrict__ b,
            float* __restrict__ C, int nrows)
{
    extern __shared__ float sh[];
    float* As = sh;             // [128][K]
    float* Ws = sh + 128 * K;   // [K][NOUT]

    const int tid  = threadIdx.x;
    const int row0 = blockIdx.x * 128;

    // load A tile (zero-pad tail rows)
    #pragma unroll 4
    for (int idx = tid; idx < 128 * K; idx += 256) {
        int r = idx / K, k = idx - r * K;
        int gr = row0 + r;
        As[idx] = (gr < nrows) ? A[(size_t)gr * lda + k] : 0.0f;
    }
    // load W (contiguous)
    #pragma unroll 4
    for (int idx = tid; idx < K * NOUT; idx += 256)
        Ws[idx] = W[idx];
    __syncthreads();

    const int tx = tid & 31;
    const int ty = tid >> 5;
    constexpr int CC = NOUT / 32;

    float acc[16][CC];
    #pragma unroll
    for (int r = 0; r < 16; r++)
        #pragma unroll
        for (int c = 0; c < CC; c++) acc[r][c] = 0.0f;

    #pragma unroll 4
    for (int k = 0; k < K; k++) {
        float w[CC];
        #pragma unroll
        for (int c = 0; c < CC; c++) w[c] = Ws[k * NOUT + tx + 32 * c];
        #pragma unroll
        for (int r = 0; r < 16; r++) {
            float a = As[(ty + 8 * r) * K + k];   // broadcast within warp
            #pragma unroll
            for (int c = 0; c < CC; c++) acc[r][c] = fmaf(a, w[c], acc[r][c]);
        }
    }

    #pragma unroll
    for (int r = 0; r < 16; r++) {
        int gr = row0 + ty + 8 * r;
        if (gr < nrows) {
            #pragma unroll
            for (int c = 0; c < CC; c++) {
                int col = tx + 32 * c;
                float v = acc[r][c];
                if (BIAS_RELU) v = fmaxf(v + b[col], 0.0f);
                C[(size_t)gr * NOUT + col] = v;
            }
        }
    }
}

// ---------------- edge scatter: agg[row] += val * s[col] ------------------
__global__ void scatter_kernel(const float* __restrict__ s,
                               const int* __restrict__ row,
                               const int* __restrict__ col,
                               const float* __restrict__ val,
                               float* __restrict__ agg, int ncols)
{
    int e    = (blockIdx.x * blockDim.x + threadIdx.x) >> 5;
    int lane = threadIdx.x & 31;
    if (e >= N_EDGES) return;
    int   r = row[e];
    int   c = col[e];
    float v = val[e];
    const float* sp = s + (size_t)c * ncols;
    float* ap = agg + (size_t)r * ncols;
    for (int j = lane; j < ncols; j += 32)
        atomicAdd(&ap[j], v * sp[j]);
}

// ---------------- bias + relu + column stats (NC = 96) --------------------
__global__ void brstats_kernel(const float* __restrict__ agg,
                               const float* __restrict__ b,
                               float* __restrict__ t)
{
    const int c  = threadIdx.x;          // 0..95
    const int y  = threadIdx.y;          // 0..3
    const float bc = b[c];
    float s = 0.0f, q = 0.0f;
    int rbase = blockIdx.x * 128 + y * 32;
    #pragma unroll 4
    for (int i = 0; i < 32; i++) {
        int r = rbase + i;
        if (r < N_NODES) {
            float v = fmaxf(agg[(size_t)r * 96 + c] + bc, 0.0f);
            t[(size_t)r * 96 + c] = v;
            s += v;
            q += v * v;
        }
    }
    atomicAdd(&g_colsum[c], (double)s);
    atomicAdd(&g_colsq [c], (double)q);
}

__global__ void finalize_stats_kernel()
{
    int c = threadIdx.x;                 // 96 threads
    double mean = g_colsum[c] / (double)N_NODES;
    double var  = g_colsq [c] / (double)N_NODES - mean * mean;
    g_mean[c] = (float)mean;
    g_rstd[c] = (float)(1.0 / sqrt(var + EPS_BN));
}

__global__ void bn_apply_kernel(const float* __restrict__ t,
                                float* __restrict__ h)
{
    const int c = threadIdx.x;
    const int y = threadIdx.y;
    const float mean = g_mean[c];
    const float rs   = g_rstd[c];
    int rbase = blockIdx.x * 128 + y * 32;
    #pragma unroll 4
    for (int i = 0; i < 32; i++) {
        int r = rbase + i;
        if (r < N_NODES)
            h[(size_t)r * 96 + c] = (t[(size_t)r * 96 + c] - mean) * rs;
    }
}

// ---------------- layer-5 relu + feat concat -------------------------------
// feat[r, 0:64]  = relu(agg64[r] + b5)
// feat[r, 64:96] = x[r, 128:160]
__global__ void build_feat_kernel(const float* __restrict__ agg64,
                                  const float* __restrict__ b5,
                                  const float* __restrict__ x,
                                  float* __restrict__ feat)
{
    const int c = threadIdx.x;           // 0..95
    const int y = threadIdx.y;
    float bc = (c < 64) ? b5[c] : 0.0f;
    int rbase = blockIdx.x * 128 + y * 32;
    #pragma unroll 4
    for (int i = 0; i < 32; i++) {
        int r = rbase + i;
        if (r < N_NODES) {
            float v;
            if (c < 64) v = fmaxf(agg64[(size_t)r * 64 + c] + bc, 0.0f);
            else        v = x[(size_t)r * XCOLS + 128 + (c - 64)];
            feat[(size_t)r * 96 + c] = v;
        }
    }
}

// ---------------- final dot (64 -> 1) + global min -------------------------
__global__ void init_min_kernel() { g_minkey = 0xFFFFFFFFu; }

__global__ void m3_kernel(const float* __restrict__ m2,
                          const float* __restrict__ M3w,
                          const float* __restrict__ M3b)
{
    int warp = (blockIdx.x * blockDim.x + threadIdx.x) >> 5;
    int lane = threadIdx.x & 31;
    if (warp >= N_NODES) return;
    float a0 = m2[(size_t)warp * 64 + lane];
    float a1 = m2[(size_t)warp * 64 + 32 + lane];
    float sum = a0 * M3w[lane] + a1 * M3w[32 + lane];
    #pragma unroll
    for (int off = 16; off > 0; off >>= 1)
        sum += __shfl_down_sync(0xFFFFFFFFu, sum, off);
    if (lane == 0) {
        float mm = sum + M3b[0];
        g_m[warp] = mm;
        atomicMin(&g_minkey, fkey(mm));
    }
}

// ---------------- group-0 replacement with global min ----------------------
__global__ void replace_kernel(const float* __restrict__ x)
{
    int i = blockIdx.x * blockDim.x + threadIdx.x;
    if (i >= N_NODES) return;
    if (x[(size_t)i * XCOLS + 160] == 0.0f)
        g_m[i] = kinv(g_minkey);
}

// ---------------- exact k-th largest via MSD radix select (1 block) -------
__global__ void select_kernel(int n, int k)
{
    __shared__ unsigned hist[256];
    __shared__ unsigned s_prefix;
    __shared__ int s_k;
    int tid = threadIdx.x;
    if (tid == 0) { s_prefix = 0u; s_k = k; }
    __syncthreads();
    for (int shift = 24; shift >= 0; shift -= 8) {
        for (int i = tid; i < 256; i += blockDim.x) hist[i] = 0u;
        __syncthreads();
        unsigned prefix = s_prefix;
        for (int i = tid; i < n; i += blockDim.x) {
            unsigned key = fkey(g_m[i]);
            if ((((unsigned long long)(key ^ prefix)) >> (shift + 8)) == 0ull)
                atomicAdd(&hist[(key >> shift) & 255u], 1u);
        }
        __syncthreads();
        if (tid == 0) {
            int kk = s_k;
            unsigned run = 0;
            for (int d = 255; d >= 0; d--) {
                unsigned h = hist[d];
                if ((unsigned)kk <= run + h) {
                    s_prefix = prefix | ((unsigned)d << shift);
                    s_k = kk - (int)run;
                    break;
                }
                run += h;
            }
        }
        __syncthreads();
    }
    if (tid == 0) g_thresh = kinv(s_prefix);
}

// ---------------- output: m * (1/m) above threshold, else 0 ----------------
__global__ void output_kernel(float* __restrict__ out)
{
    int i = blockIdx.x * blockDim.x + threadIdx.x;
    if (i >= N_NODES) return;
    float mm = g_m[i];
    out[i] = (mm > g_thresh) ? mm * (1.0f / mm) : 0.0f;
}

// ===========================================================================
extern "C" void kernel_launch(void* const* d_in, const int* in_sizes, int n_in,
                              void* d_out, int out_size)
{
    const float* x    = (const float*)d_in[0];
    const int*   row  = (const int*)  d_in[1];
    const int*   col  = (const int*)  d_in[2];
    const float* val  = (const float*)d_in[3];
    const float* W[5] = {(const float*)d_in[4], (const float*)d_in[6],
                         (const float*)d_in[8], (const float*)d_in[10],
                         (const float*)d_in[12]};
    const float* B[5] = {(const float*)d_in[5], (const float*)d_in[7],
                         (const float*)d_in[9], (const float*)d_in[11],
                         (const float*)d_in[13]};
    const float* M1w = (const float*)d_in[14];
    const float* M1b = (const float*)d_in[15];
    const float* M2w = (const float*)d_in[16];
    const float* M2b = (const float*)d_in[17];
    const float* M3w = (const float*)d_in[18];
    const float* M3b = (const float*)d_in[19];
    float* out = (float*)d_out;

    // scratch symbol addresses
    float *h, *s, *agg;
    double *csum, *csq;
    cudaGetSymbolAddress((void**)&h,    g_h);
    cudaGetSymbolAddress((void**)&s,    g_s);
    cudaGetSymbolAddress((void**)&agg,  g_agg);
    cudaGetSymbolAddress((void**)&csum, g_colsum);
    cudaGetSymbolAddress((void**)&csq,  g_colsq);

    // opt-in dynamic smem sizes per GEMM instantiation
    const int sm_128_96  = (128 * 128 + 128 * 96) * 4;  // 114688
    const int sm_96_96   = (128 * 96  + 96  * 96) * 4;  //  86016
    const int sm_96_64   = (128 * 96  + 96  * 64) * 4;  //  73728
    const int sm_96_128  = (128 * 96  + 96  * 128) * 4; //  98304
    const int sm_128_64  = (128 * 128 + 128 * 64) * 4;  //  98304
    cudaFuncSetAttribute(gemm_kernel<128, 96,  false>, cudaFuncAttributeMaxDynamicSharedMemorySize, sm_128_96);
    cudaFuncSetAttribute(gemm_kernel<96,  96,  false>, cudaFuncAttributeMaxDynamicSharedMemorySize, sm_96_96);
    cudaFuncSetAttribute(gemm_kernel<96,  64,  false>, cudaFuncAttributeMaxDynamicSharedMemorySize, sm_96_64);
    cudaFuncSetAttribute(gemm_kernel<96,  128, true >, cudaFuncAttributeMaxDynamicSharedMemorySize, sm_96_128);
    cudaFuncSetAttribute(gemm_kernel<128, 64,  true >, cudaFuncAttributeMaxDynamicSharedMemorySize, sm_128_64);

    const dim3 grid_g((N_NODES + 127) / 128);
    const dim3 blk_g(256);
    const dim3 grid_cw((N_NODES + 127) / 128);
    const dim3 blk_cw(96, 4);
    const int  grid_e = (N_EDGES + 7) / 8;   // 8 warps (edges) per 256-thr block

    // ---------------- GCN layer 1 (K=128 from x) ----------------
    gemm_kernel<128, 96, false><<<grid_g, blk_g, sm_128_96>>>(x, XCOLS, W[0], nullptr, s, N_NODES);
    cudaMemsetAsync(agg, 0, (size_t)N_NODES * 96 * 4);
    scatter_kernel<<<grid_e, 256>>>(s, row, col, val, agg, 96);
    cudaMemsetAsync(csum, 0, 96 * sizeof(double));
    cudaMemsetAsync(csq,  0, 96 * sizeof(double));
    brstats_kernel<<<grid_cw, blk_cw>>>(agg, B[0], s);
    finalize_stats_kernel<<<1, 96>>>();
    bn_apply_kernel<<<grid_cw, blk_cw>>>(s, h);

    // ---------------- GCN layers 2-4 (K=96) ----------------
    for (int l = 1; l <= 3; l++) {
        gemm_kernel<96, 96, false><<<grid_g, blk_g, sm_96_96>>>(h, 96, W[l], nullptr, s, N_NODES);
        cudaMemsetAsync(agg, 0, (size_t)N_NODES * 96 * 4);
        scatter_kernel<<<grid_e, 256>>>(s, row, col, val, agg, 96);
        cudaMemsetAsync(csum, 0, 96 * sizeof(double));
        cudaMemsetAsync(csq,  0, 96 * sizeof(double));
        brstats_kernel<<<grid_cw, blk_cw>>>(agg, B[l], s);
        finalize_stats_kernel<<<1, 96>>>();
        bn_apply_kernel<<<grid_cw, blk_cw>>>(s, h);
    }

    // ---------------- GCN layer 5 (K=96 -> 64, relu only) ----------------
    gemm_kernel<96, 64, false><<<grid_g, blk_g, sm_96_64>>>(h, 96, W[4], nullptr, s, N_NODES);
    cudaMemsetAsync(agg, 0, (size_t)N_NODES * 64 * 4);
    scatter_kernel<<<grid_e, 256>>>(s, row, col, val, agg, 64);
    // feat = [relu(agg + b5) | x[:,128:160]]  -> s (N x 96)
    build_feat_kernel<<<grid_cw, blk_cw>>>(agg, B[4], x, s);

    // ---------------- MLP ----------------
    gemm_kernel<96, 128, true><<<grid_g, blk_g, sm_96_128>>>(s, 96, M1w, M1b, agg, N_NODES);
    gemm_kernel<128, 64, true><<<grid_g, blk_g, sm_128_64>>>(agg, 128, M2w, M2b, h, N_NODES);
    init_min_kernel<<<1, 1>>>();
    m3_kernel<<<(N_NODES * 32 + 255) / 256, 256>>>(h, M3w, M3b);

    // ---------------- min-replacement, top-k threshold, output ----------------
    replace_kernel<<<(N_NODES + 255) / 256, 256>>>(x);
    select_kernel<<<1, 1024>>>(N_NODES, KTOP);
    output_kernel<<<(N_NODES + 255) / 256, 256>>>(out);
}

// round 11
// speedup vs baseline: 1.0059x; 1.0059x over previous
#include <cuda_runtime.h>
#include <math.h>

// Problem constants (fixed by dataset)
#define N_NODES 50000
#define N_EDGES 800000
#define XCOLS   161       // NFEAT(128) + EXTRA(32) + 1
#define KTOP    71        // NN + 1
#define EPS_BN  1e-5

// ---------------- device scratch (static, allocation-free) ----------------
__device__ float   g_h  [N_NODES * 128];
__device__ float   g_s  [N_NODES * 128];
__device__ float   g_agg[N_NODES * 128];
__device__ double  g_colsum[128];
__device__ double  g_colsq [128];
__device__ float   g_mean[128];
__device__ float   g_rstd[128];
__device__ float   g_m[N_NODES];
__device__ unsigned g_minkey;
__device__ float   g_thresh;

// monotonic float<->uint key (ascending uint == ascending float)
__device__ __forceinline__ unsigned fkey(float x) {
    unsigned u = __float_as_uint(x);
    return (u & 0x80000000u) ? ~u : (u | 0x80000000u);
}
__device__ __forceinline__ float kinv(unsigned k) {
    unsigned u = (k & 0x80000000u) ? (k & 0x7FFFFFFFu) : ~k;
    return __uint_as_float(u);
}

// ---------------- GEMM: C[n,NOUT] = A[n,K] @ W[K,NOUT] (+bias,relu) -------
// block = 256 threads. tx = tid&31 -> column lane, ty = tid>>5 -> row group.
// Block tile: 128 rows x NOUT cols. Each thread: 16 rows x NOUT/32 cols.
// A tile + full W staged in dynamic shared memory. Coalesced stores.
template <int K, int NOUT, bool BIAS_RELU>
__global__ void __launch_bounds__(256)
gemm_kernel(const float* __restrict__ A, int lda,
            const float* __restrict__ W, const float* __restrict__ b,
            float* __restrict__ C, int nrows)
{
    extern __shared__ float sh[];
    float* As = sh;             // [128][K]
    float* Ws = sh + 128 * K;   // [K][NOUT]

    const int tid  = threadIdx.x;
    const int row0 = blockIdx.x * 128;

    // load A tile (zero-pad tail rows)
    #pragma unroll 4
    for (int idx = tid; idx < 128 * K; idx += 256) {
        int r = idx / K, k = idx - r * K;
        int gr = row0 + r;
        As[idx] = (gr < nrows) ? A[(size_t)gr * lda + k] : 0.0f;
    }
    // load W (contiguous)
    #pragma unroll 4
    for (int idx = tid; idx < K * NOUT; idx += 256)
        Ws[idx] = W[idx];
    __syncthreads();

    const int tx = tid & 31;
    const int ty = tid >> 5;
    constexpr int CC = NOUT / 32;

    float acc[16][CC];
    #pragma unroll
    for (int r = 0; r < 16; r++)
        #pragma unroll
        for (int c = 0; c < CC; c++) acc[r][c] = 0.0f;

    #pragma unroll 4
    for (int k = 0; k < K; k++) {
        float w[CC];
        #pragma unroll
        for (int c = 0; c < CC; c++) w[c] = Ws[k * NOUT + tx + 32 * c];
        #pragma unroll
        for (int r = 0; r < 16; r++) {
            float a = As[(ty + 8 * r) * K + k];   // broadcast within warp
            #pragma unroll
            for (int c = 0; c < CC; c++) acc[r][c] = fmaf(a, w[c], acc[r][c]);
        }
    }

    #pragma unroll
    for (int r = 0; r < 16; r++) {
        int gr = row0 + ty + 8 * r;
        if (gr < nrows) {
            #pragma unroll
            for (int c = 0; c < CC; c++) {
                int col = tx + 32 * c;
                float v = acc[r][c];
                if (BIAS_RELU) v = fmaxf(v + b[col], 0.0f);
                C[(size_t)gr * NOUT + col] = v;
            }
        }
    }
}

// ---------------- edge scatter: agg[row] += val * s[col] ------------------
__global__ void scatter_kernel(const float* __restrict__ s,
                               const int* __restrict__ row,
                               const int* __restrict__ col,
                               const float* __restrict__ val,
                               float* __restrict__ agg, int ncols)
{
    int e    = (blockIdx.x * blockDim.x + threadIdx.x) >> 5;
    int lane = threadIdx.x & 31;
    if (e >= N_EDGES) return;
    int   r = row[e];
    int   c = col[e];
    float v = val[e];
    const float* sp = s + (size_t)c * ncols;
    float* ap = agg + (size_t)r * ncols;
    for (int j = lane; j < ncols; j += 32)
        atomicAdd(&ap[j], v * sp[j]);
}

// ---------------- bias + relu + column stats (NC = 96) --------------------
__global__ void brstats_kernel(const float* __restrict__ agg,
                               const float* __restrict__ b,
                               float* __restrict__ t)
{
    const int c  = threadIdx.x;          // 0..95
    const int y  = threadIdx.y;          // 0..3
    const float bc = b[c];
    float s = 0.0f, q = 0.0f;
    int rbase = blockIdx.x * 128 + y * 32;
    #pragma unroll 4
    for (int i = 0; i < 32; i++) {
        int r = rbase + i;
        if (r < N_NODES) {
            float v = fmaxf(agg[(size_t)r * 96 + c] + bc, 0.0f);
            t[(size_t)r * 96 + c] = v;
            s += v;
            q += v * v;
        }
    }
    atomicAdd(&g_colsum[c], (double)s);
    atomicAdd(&g_colsq [c], (double)q);
}

__global__ void finalize_stats_kernel()
{
    int c = threadIdx.x;                 // 96 threads
    double mean = g_colsum[c] / (double)N_NODES;
    double var  = g_colsq [c] / (double)N_NODES - mean * mean;
    g_mean[c] = (float)mean;
    g_rstd[c] = (float)(1.0 / sqrt(var + EPS_BN));
}

__global__ void bn_apply_kernel(const float* __restrict__ t,
                                float* __restrict__ h)
{
    const int c = threadIdx.x;
    const int y = threadIdx.y;
    const float mean = g_mean[c];
    const float rs   = g_rstd[c];
    int rbase = blockIdx.x * 128 + y * 32;
    #pragma unroll 4
    for (int i = 0; i < 32; i++) {
        int r = rbase + i;
        if (r < N_NODES)
            h[(size_t)r * 96 + c] = (t[(size_t)r * 96 + c] - mean) * rs;
    }
}

// ---------------- layer-5 relu + feat concat -------------------------------
// feat[r, 0:64]  = relu(agg64[r] + b5)
// feat[r, 64:96] = x[r, 128:160]
__global__ void build_feat_kernel(const float* __restrict__ agg64,
                                  const float* __restrict__ b5,
                                  const float* __restrict__ x,
                                  float* __restrict__ feat)
{
    const int c = threadIdx.x;           // 0..95
    const int y = threadIdx.y;
    float bc = (c < 64) ? b5[c] : 0.0f;
    int rbase = blockIdx.x * 128 + y * 32;
    #pragma unroll 4
    for (int i = 0; i < 32; i++) {
        int r = rbase + i;
        if (r < N_NODES) {
            float v;
            if (c < 64) v = fmaxf(agg64[(size_t)r * 64 + c] + bc, 0.0f);
            else        v = x[(size_t)r * XCOLS + 128 + (c - 64)];
            feat[(size_t)r * 96 + c] = v;
        }
    }
}

// ---------------- final dot (64 -> 1) + global min -------------------------
__global__ void init_min_kernel() { g_minkey = 0xFFFFFFFFu; }

__global__ void m3_kernel(const float* __restrict__ m2,
                          const float* __restrict__ M3w,
                          const float* __restrict__ M3b)
{
    int warp = (blockIdx.x * blockDim.x + threadIdx.x) >> 5;
    int lane = threadIdx.x & 31;
    if (warp >= N_NODES) return;
    float a0 = m2[(size_t)warp * 64 + lane];
    float a1 = m2[(size_t)warp * 64 + 32 + lane];
    float sum = a0 * M3w[lane] + a1 * M3w[32 + lane];
    #pragma unroll
    for (int off = 16; off > 0; off >>= 1)
        sum += __shfl_down_sync(0xFFFFFFFFu, sum, off);
    if (lane == 0) {
        float mm = sum + M3b[0];
        g_m[warp] = mm;
        atomicMin(&g_minkey, fkey(mm));
    }
}

// ---------------- group-0 replacement with global min ----------------------
__global__ void replace_kernel(const float* __restrict__ x)
{
    int i = blockIdx.x * blockDim.x + threadIdx.x;
    if (i >= N_NODES) return;
    if (x[(size_t)i * XCOLS + 160] == 0.0f)
        g_m[i] = kinv(g_minkey);
}

// ---------------- exact k-th largest via MSD radix select (1 block) -------
__global__ void select_kernel(int n, int k)
{
    __shared__ unsigned hist[256];
    __shared__ unsigned s_prefix;
    __shared__ int s_k;
    int tid = threadIdx.x;
    if (tid == 0) { s_prefix = 0u; s_k = k; }
    __syncthreads();
    for (int shift = 24; shift >= 0; shift -= 8) {
        for (int i = tid; i < 256; i += blockDim.x) hist[i] = 0u;
        __syncthreads();
        unsigned prefix = s_prefix;
        for (int i = tid; i < n; i += blockDim.x) {
            unsigned key = fkey(g_m[i]);
            if ((((unsigned long long)(key ^ prefix)) >> (shift + 8)) == 0ull)
                atomicAdd(&hist[(key >> shift) & 255u], 1u);
        }
        __syncthreads();
        if (tid == 0) {
            int kk = s_k;
            unsigned run = 0;
            for (int d = 255; d >= 0; d--) {
                unsigned h = hist[d];
                if ((unsigned)kk <= run + h) {
                    s_prefix = prefix | ((unsigned)d << shift);
                    s_k = kk - (int)run;
                    break;
                }
                run += h;
            }
        }
        __syncthreads();
    }
    if (tid == 0) g_thresh = kinv(s_prefix);
}

// ---------------- output: m * (1/m) above threshold, else 0 ----------------
__global__ void output_kernel(float* __restrict__ out)
{
    int i = blockIdx.x * blockDim.x + threadIdx.x;
    if (i >= N_NODES) return;
    float mm = g_m[i];
    out[i] = (mm > g_thresh) ? mm * (1.0f / mm) : 0.0f;
}

// ===========================================================================
extern "C" void kernel_launch(void* const* d_in, const int* in_sizes, int n_in,
                              void* d_out, int out_size)
{
    const float* x    = (const float*)d_in[0];
    const int*   row  = (const int*)  d_in[1];
    const int*   col  = (const int*)  d_in[2];
    const float* val  = (const float*)d_in[3];
    const float* W[5] = {(const float*)d_in[4], (const float*)d_in[6],
                         (const float*)d_in[8], (const float*)d_in[10],
                         (const float*)d_in[12]};
    const float* B[5] = {(const float*)d_in[5], (const float*)d_in[7],
                         (const float*)d_in[9], (const float*)d_in[11],
                         (const float*)d_in[13]};
    const float* M1w = (const float*)d_in[14];
    const float* M1b = (const float*)d_in[15];
    const float* M2w = (const float*)d_in[16];
    const float* M2b = (const float*)d_in[17];
    const float* M3w = (const float*)d_in[18];
    const float* M3b = (const float*)d_in[19];
    float* out = (float*)d_out;

    // scratch symbol addresses
    float *h, *s, *agg;
    double *csum, *csq;
    cudaGetSymbolAddress((void**)&h,    g_h);
    cudaGetSymbolAddress((void**)&s,    g_s);
    cudaGetSymbolAddress((void**)&agg,  g_agg);
    cudaGetSymbolAddress((void**)&csum, g_colsum);
    cudaGetSymbolAddress((void**)&csq,  g_colsq);

    // opt-in dynamic smem sizes per GEMM instantiation
    const int sm_128_96  = (128 * 128 + 128 * 96) * 4;  // 114688
    const int sm_96_96   = (128 * 96  + 96  * 96) * 4;  //  86016
    const int sm_96_64   = (128 * 96  + 96  * 64) * 4;  //  73728
    const int sm_96_128  = (128 * 96  + 96  * 128) * 4; //  98304
    const int sm_128_64  = (128 * 128 + 128 * 64) * 4;  //  98304
    cudaFuncSetAttribute(gemm_kernel<128, 96,  false>, cudaFuncAttributeMaxDynamicSharedMemorySize, sm_128_96);
    cudaFuncSetAttribute(gemm_kernel<96,  96,  false>, cudaFuncAttributeMaxDynamicSharedMemorySize, sm_96_96);
    cudaFuncSetAttribute(gemm_kernel<96,  64,  false>, cudaFuncAttributeMaxDynamicSharedMemorySize, sm_96_64);
    cudaFuncSetAttribute(gemm_kernel<96,  128, true >, cudaFuncAttributeMaxDynamicSharedMemorySize, sm_96_128);
    cudaFuncSetAttribute(gemm_kernel<128, 64,  true >, cudaFuncAttributeMaxDynamicSharedMemorySize, sm_128_64);

    const dim3 grid_g((N_NODES + 127) / 128);
    const dim3 blk_g(256);
    const dim3 grid_cw((N_NODES + 127) / 128);
    const dim3 blk_cw(96, 4);
    const int  grid_e = (N_EDGES + 7) / 8;   // 8 warps (edges) per 256-thr block

    // ---------------- GCN layer 1 (K=128 from x) ----------------
    gemm_kernel<128, 96, false><<<grid_g, blk_g, sm_128_96>>>(x, XCOLS, W[0], nullptr, s, N_NODES);
    cudaMemsetAsync(agg, 0, (size_t)N_NODES * 96 * 4);
    scatter_kernel<<<grid_e, 256>>>(s, row, col, val, agg, 96);
    cudaMemsetAsync(csum, 0, 96 * sizeof(double));
    cudaMemsetAsync(csq,  0, 96 * sizeof(double));
    brstats_kernel<<<grid_cw, blk_cw>>>(agg, B[0], s);
    finalize_stats_kernel<<<1, 96>>>();
    bn_apply_kernel<<<grid_cw, blk_cw>>>(s, h);

    // ---------------- GCN layers 2-4 (K=96) ----------------
    for (int l = 1; l <= 3; l++) {
        gemm_kernel<96, 96, false><<<grid_g, blk_g, sm_96_96>>>(h, 96, W[l], nullptr, s, N_NODES);
        cudaMemsetAsync(agg, 0, (size_t)N_NODES * 96 * 4);
        scatter_kernel<<<grid_e, 256>>>(s, row, col, val, agg, 96);
        cudaMemsetAsync(csum, 0, 96 * sizeof(double));
        cudaMemsetAsync(csq,  0, 96 * sizeof(double));
        brstats_kernel<<<grid_cw, blk_cw>>>(agg, B[l], s);
        finalize_stats_kernel<<<1, 96>>>();
        bn_apply_kernel<<<grid_cw, blk_cw>>>(s, h);
    }

    // ---------------- GCN layer 5 (K=96 -> 64, relu only) ----------------
    gemm_kernel<96, 64, false><<<grid_g, blk_g, sm_96_64>>>(h, 96, W[4], nullptr, s, N_NODES);
    cudaMemsetAsync(agg, 0, (size_t)N_NODES * 64 * 4);
    scatter_kernel<<<grid_e, 256>>>(s, row, col, val, agg, 64);
    // feat = [relu(agg + b5) | x[:,128:160]]  -> s (N x 96)
    build_feat_kernel<<<grid_cw, blk_cw>>>(agg, B[4], x, s);

    // ---------------- MLP ----------------
    gemm_kernel<96, 128, true><<<grid_g, blk_g, sm_96_128>>>(s, 96, M1w, M1b, agg, N_NODES);
    gemm_kernel<128, 64, true><<<grid_g, blk_g, sm_128_64>>>(agg, 128, M2w, M2b, h, N_NODES);
    init_min_kernel<<<1, 1>>>();
    m3_kernel<<<(N_NODES * 32 + 255) / 256, 256>>>(h, M3w, M3b);

    // ---------------- min-replacement, top-k threshold, output ----------------
    replace_kernel<<<(N_NODES + 255) / 256, 256>>>(x);
    select_kernel<<<1, 1024>>>(N_NODES, KTOP);
    output_kernel<<<(N_NODES + 255) / 256, 256>>>(out);
}